// round 2
// baseline (speedup 1.0000x reference)
#include <cuda_runtime.h>

// Scratch for reciprocal norms: N = 100000 rows (fixed by the problem).
#define N_MAX 100000
__device__ float g_rnorm[N_MAX];

// Kernel 1: one warp per row. 32 lanes x float4 = 128 elements.
__global__ void rnorm_kernel(const float* __restrict__ x, int n) {
    int warp = (blockIdx.x * blockDim.x + threadIdx.x) >> 5;
    int lane = threadIdx.x & 31;
    if (warp >= n) return;
    const float4* row = reinterpret_cast<const float4*>(x + (size_t)warp * 128);
    float4 v = __ldg(row + lane);
    float ss = v.x * v.x + v.y * v.y + v.z * v.z + v.w * v.w;
#pragma unroll
    for (int o = 16; o; o >>= 1) ss += __shfl_xor_sync(0xffffffffu, ss, o);
    if (lane == 0) g_rnorm[warp] = 1.0f / fmaxf(sqrtf(ss), 1e-12f);
}

// Kernel 2: one warp per edge. Indices are int32 (JAX canonicalizes int64
// to int32 without x64 mode). Each lane loads one float4 from the src row
// and one from the dst row (512B coalesced per row), FMA, shuffle-reduce,
// lane 0 scales by rnorm[s]*rnorm[d] and stores.
__global__ void edge_dot_kernel(const float* __restrict__ x,
                                const int* __restrict__ src,
                                const int* __restrict__ dst,
                                float* __restrict__ out, int e, int n) {
    int warp = (blockIdx.x * blockDim.x + threadIdx.x) >> 5;
    int lane = threadIdx.x & 31;
    if (warp >= e) return;
    int s = __ldg(src + warp);   // same addr across warp -> broadcast
    int d = __ldg(dst + warp);
    // Defensive: never fault even if dtype assumption is wrong.
    if ((unsigned)s >= (unsigned)n || (unsigned)d >= (unsigned)n) {
        if (lane == 0) out[warp] = 0.0f;
        return;
    }
    const float4* rs = reinterpret_cast<const float4*>(x + (size_t)s * 128);
    const float4* rd = reinterpret_cast<const float4*>(x + (size_t)d * 128);
    float4 a = __ldg(rs + lane);
    float4 b = __ldg(rd + lane);
    float acc = a.x * b.x;
    acc = fmaf(a.y, b.y, acc);
    acc = fmaf(a.z, b.z, acc);
    acc = fmaf(a.w, b.w, acc);
#pragma unroll
    for (int o = 16; o; o >>= 1) acc += __shfl_xor_sync(0xffffffffu, acc, o);
    if (lane == 0) {
        out[warp] = acc * __ldg(&g_rnorm[s]) * __ldg(&g_rnorm[d]);
    }
}

extern "C" void kernel_launch(void* const* d_in, const int* in_sizes, int n_in,
                              void* d_out, int out_size) {
    const float* x   = (const float*)d_in[0];
    const int*   src = (const int*)d_in[1];
    const int*   dst = (const int*)d_in[2];
    float*       out = (float*)d_out;

    int n = in_sizes[0] / 128;   // 100000
    int e = in_sizes[1];         // 640000

    int nblk1 = (n + 7) / 8;     // 8 warps / 256-thread block
    rnorm_kernel<<<nblk1, 256>>>(x, n);

    int nblk2 = (e + 7) / 8;
    edge_dot_kernel<<<nblk2, 256>>>(x, src, dst, out, e, n);
}

// round 3
// speedup vs baseline: 1.2782x; 1.2782x over previous
#include <cuda_runtime.h>

#define N_MAX 100000
#define D 128
// Normalized copy of x: 100000 x 128 fp32 = 51.2 MB (fits in L2 alongside traffic).
__device__ float g_xn[N_MAX * D];

// Kernel 1: one warp per row. Compute 1/max(||row||,eps), write normalized row.
__global__ void normalize_kernel(const float* __restrict__ x, int n) {
    int warp = (blockIdx.x * blockDim.x + threadIdx.x) >> 5;
    int lane = threadIdx.x & 31;
    if (warp >= n) return;
    const float4* row = reinterpret_cast<const float4*>(x + (size_t)warp * D);
    float4 v = __ldg(row + lane);
    float ss = v.x * v.x + v.y * v.y + v.z * v.z + v.w * v.w;
#pragma unroll
    for (int o = 16; o; o >>= 1) ss += __shfl_xor_sync(0xffffffffu, ss, o);
    float r = 1.0f / fmaxf(sqrtf(ss), 1e-12f);   // all lanes have it post-butterfly
    float4 w = make_float4(v.x * r, v.y * r, v.z * r, v.w * r);
    reinterpret_cast<float4*>(g_xn + (size_t)warp * D)[lane] = w;
}

// Kernel 2: one warp handles 4 edges (8 row gathers in flight).
// Lanes 0..7 load the 8 indices; broadcast via shfl. Each lane loads one
// float4 per row (512B coalesced). Butterfly reduction interleaved over the
// 4 accumulators; lane 0 stores all 4 scores with a single STG.128.
__global__ void edge_dot_kernel(const int* __restrict__ src,
                                const int* __restrict__ dst,
                                float* __restrict__ out, int e, int n) {
    int warp = (blockIdx.x * blockDim.x + threadIdx.x) >> 5;
    int lane = threadIdx.x & 31;
    int e0 = warp * 4;
    if (e0 >= e) return;

    // lanes 0..3 -> src[e0+lane], lanes 4..7 -> dst[e0+lane-4]
    int myidx = 0;
    if (lane < 8) {
        int k = e0 + (lane & 3);
        myidx = (lane < 4) ? __ldg(src + k) : __ldg(dst + k);
        if ((unsigned)myidx >= (unsigned)n) myidx = 0;  // defensive, never fires
    }

    float acc0, acc1, acc2, acc3;
    {
        int s0 = __shfl_sync(0xffffffffu, myidx, 0);
        int s1 = __shfl_sync(0xffffffffu, myidx, 1);
        int s2 = __shfl_sync(0xffffffffu, myidx, 2);
        int s3 = __shfl_sync(0xffffffffu, myidx, 3);
        int d0 = __shfl_sync(0xffffffffu, myidx, 4);
        int d1 = __shfl_sync(0xffffffffu, myidx, 5);
        int d2 = __shfl_sync(0xffffffffu, myidx, 6);
        int d3 = __shfl_sync(0xffffffffu, myidx, 7);

        const float4* base = reinterpret_cast<const float4*>(g_xn);
        // row stride in float4 units = 32
        float4 a0 = base[(size_t)s0 * 32 + lane];
        float4 b0 = base[(size_t)d0 * 32 + lane];
        float4 a1 = base[(size_t)s1 * 32 + lane];
        float4 b1 = base[(size_t)d1 * 32 + lane];
        float4 a2 = base[(size_t)s2 * 32 + lane];
        float4 b2 = base[(size_t)d2 * 32 + lane];
        float4 a3 = base[(size_t)s3 * 32 + lane];
        float4 b3 = base[(size_t)d3 * 32 + lane];

        acc0 = fmaf(a0.w, b0.w, fmaf(a0.z, b0.z, fmaf(a0.y, b0.y, a0.x * b0.x)));
        acc1 = fmaf(a1.w, b1.w, fmaf(a1.z, b1.z, fmaf(a1.y, b1.y, a1.x * b1.x)));
        acc2 = fmaf(a2.w, b2.w, fmaf(a2.z, b2.z, fmaf(a2.y, b2.y, a2.x * b2.x)));
        acc3 = fmaf(a3.w, b3.w, fmaf(a3.z, b3.z, fmaf(a3.y, b3.y, a3.x * b3.x)));
    }

#pragma unroll
    for (int o = 16; o; o >>= 1) {
        acc0 += __shfl_xor_sync(0xffffffffu, acc0, o);
        acc1 += __shfl_xor_sync(0xffffffffu, acc1, o);
        acc2 += __shfl_xor_sync(0xffffffffu, acc2, o);
        acc3 += __shfl_xor_sync(0xffffffffu, acc3, o);
    }

    if (lane == 0) {
        // e0 is a multiple of 4 -> out+e0 is 16B aligned; E=640000 divisible by 4.
        *reinterpret_cast<float4*>(out + e0) = make_float4(acc0, acc1, acc2, acc3);
    }
}

extern "C" void kernel_launch(void* const* d_in, const int* in_sizes, int n_in,
                              void* d_out, int out_size) {
    const float* x   = (const float*)d_in[0];
    const int*   src = (const int*)d_in[1];
    const int*   dst = (const int*)d_in[2];
    float*       out = (float*)d_out;

    int n = in_sizes[0] / D;   // 100000
    int e = in_sizes[1];       // 640000

    int nblk1 = (n + 7) / 8;                 // 8 warps/block
    normalize_kernel<<<nblk1, 256>>>(x, n);

    int warps = (e + 3) / 4;
    int nblk2 = (warps + 7) / 8;
    edge_dot_kernel<<<nblk2, 256>>>(src, dst, out, e, n);
}

// round 4
// speedup vs baseline: 1.7201x; 1.3457x over previous
#include <cuda_runtime.h>
#include <cuda_fp16.h>

#define N_MAX 100000
#define D 128
// Normalized rows in fp16: 100000 x 128 x 2B = 25.6 MB (L2-resident).
__device__ __half g_xh[N_MAX * D];

// Kernel 1: one warp per row. Compute 1/max(||row||,eps) in fp32, write fp16.
__global__ void normalize_kernel(const float* __restrict__ x, int n) {
    int warp = (blockIdx.x * blockDim.x + threadIdx.x) >> 5;
    int lane = threadIdx.x & 31;
    if (warp >= n) return;
    const float4* row = reinterpret_cast<const float4*>(x + (size_t)warp * D);
    float4 v = __ldg(row + lane);
    float ss = v.x * v.x + v.y * v.y + v.z * v.z + v.w * v.w;
#pragma unroll
    for (int o = 16; o; o >>= 1) ss += __shfl_xor_sync(0xffffffffu, ss, o);
    float r = 1.0f / fmaxf(sqrtf(ss), 1e-12f);
    __half2 h0 = __floats2half2_rn(v.x * r, v.y * r);
    __half2 h1 = __floats2half2_rn(v.z * r, v.w * r);
    // lane owns elements [4*lane .. 4*lane+3] -> 8 bytes at uint2 slot `lane`
    uint2 packed;
    packed.x = *reinterpret_cast<unsigned*>(&h0);
    packed.y = *reinterpret_cast<unsigned*>(&h1);
    reinterpret_cast<uint2*>(g_xh + (size_t)warp * D)[lane] = packed;
}

__device__ __forceinline__ float dot8b(uint2 a, uint2 b) {
    __half2 a0 = *reinterpret_cast<__half2*>(&a.x);
    __half2 a1 = *reinterpret_cast<__half2*>(&a.y);
    __half2 b0 = *reinterpret_cast<__half2*>(&b.x);
    __half2 b1 = *reinterpret_cast<__half2*>(&b.y);
    float2 fa0 = __half22float2(a0), fa1 = __half22float2(a1);
    float2 fb0 = __half22float2(b0), fb1 = __half22float2(b1);
    float acc = fa0.x * fb0.x;
    acc = fmaf(fa0.y, fb0.y, acc);
    acc = fmaf(fa1.x, fb1.x, acc);
    acc = fmaf(fa1.y, fb1.y, acc);
    return acc;
}

// Kernel 2: one warp handles 8 edges (16 row gathers of 256B each in flight).
// Lanes 0..15 load the 16 indices, broadcast by shfl. Each lane loads one
// uint2 (4 halves) per row. Butterfly reduction interleaved across the 8
// accumulators; lane 0 stores all 8 scores with two STG.128.
__global__ void __launch_bounds__(256, 4)
edge_dot_kernel(const int* __restrict__ src,
                const int* __restrict__ dst,
                float* __restrict__ out, int e, int n) {
    int warp = (blockIdx.x * blockDim.x + threadIdx.x) >> 5;
    int lane = threadIdx.x & 31;
    int e0 = warp * 8;
    if (e0 >= e) return;

    // lanes 0..7 -> src[e0+lane], lanes 8..15 -> dst[e0+lane-8]
    int myidx = 0;
    if (lane < 16) {
        int k = e0 + (lane & 7);
        myidx = (lane < 8) ? __ldg(src + k) : __ldg(dst + k);
        if ((unsigned)myidx >= (unsigned)n) myidx = 0;  // defensive, never fires
    }

    const uint2* base = reinterpret_cast<const uint2*>(g_xh);  // row stride 32

    int s[8], d[8];
#pragma unroll
    for (int j = 0; j < 8; j++) {
        s[j] = __shfl_sync(0xffffffffu, myidx, j);
        d[j] = __shfl_sync(0xffffffffu, myidx, j + 8);
    }

    uint2 a[8], b[8];
#pragma unroll
    for (int j = 0; j < 8; j++) a[j] = __ldg(base + (size_t)s[j] * 32 + lane);
#pragma unroll
    for (int j = 0; j < 8; j++) b[j] = __ldg(base + (size_t)d[j] * 32 + lane);

    float acc[8];
#pragma unroll
    for (int j = 0; j < 8; j++) acc[j] = dot8b(a[j], b[j]);

#pragma unroll
    for (int o = 16; o; o >>= 1) {
#pragma unroll
        for (int j = 0; j < 8; j++)
            acc[j] += __shfl_xor_sync(0xffffffffu, acc[j], o);
    }

    if (lane == 0) {
        // e0 multiple of 8 -> 16B aligned; E divisible by 8.
        float4* o4 = reinterpret_cast<float4*>(out + e0);
        o4[0] = make_float4(acc[0], acc[1], acc[2], acc[3]);
        o4[1] = make_float4(acc[4], acc[5], acc[6], acc[7]);
    }
}

extern "C" void kernel_launch(void* const* d_in, const int* in_sizes, int n_in,
                              void* d_out, int out_size) {
    const float* x   = (const float*)d_in[0];
    const int*   src = (const int*)d_in[1];
    const int*   dst = (const int*)d_in[2];
    float*       out = (float*)d_out;

    int n = in_sizes[0] / D;   // 100000
    int e = in_sizes[1];       // 640000

    int nblk1 = (n + 7) / 8;                 // 8 warps/block
    normalize_kernel<<<nblk1, 256>>>(x, n);

    int warps = (e + 7) / 8;
    int nblk2 = (warps + 7) / 8;
    edge_dot_kernel<<<nblk2, 256>>>(src, dst, out, e, n);
}

// round 5
// speedup vs baseline: 2.2934x; 1.3333x over previous
#include <cuda_runtime.h>
#include <cuda_fp16.h>

#define N_MAX 100000
#define D 128
// Normalized rows in fp16: 100000 x 128 x 2B = 25.6 MB (L2-resident).
__device__ __half g_xh[N_MAX * D];

// Kernel 1: one warp per row. fp32 norm, write fp16 row.
__global__ void normalize_kernel(const float* __restrict__ x, int n) {
    int warp = (blockIdx.x * blockDim.x + threadIdx.x) >> 5;
    int lane = threadIdx.x & 31;
    if (warp >= n) return;
    const float4* row = reinterpret_cast<const float4*>(x + (size_t)warp * D);
    float4 v = __ldg(row + lane);
    float ss = v.x * v.x + v.y * v.y + v.z * v.z + v.w * v.w;
#pragma unroll
    for (int o = 16; o; o >>= 1) ss += __shfl_xor_sync(0xffffffffu, ss, o);
    float r = 1.0f / fmaxf(sqrtf(ss), 1e-12f);
    __half2 h0 = __floats2half2_rn(v.x * r, v.y * r);
    __half2 h1 = __floats2half2_rn(v.z * r, v.w * r);
    uint2 packed;
    packed.x = *reinterpret_cast<unsigned*>(&h0);
    packed.y = *reinterpret_cast<unsigned*>(&h1);
    reinterpret_cast<uint2*>(g_xh + (size_t)warp * D)[lane] = packed;
}

// Kernel 2: one warp = 8 edges. Each LDG.128 gathers TWO rows (16 lanes x 16B
// per row). 8 gather instructions per warp (4 src pairs + 4 dst pairs).
// half2 multiply/fma with early fp32 conversion; value-packing butterfly
// reduces all 8 edges in 8 SHFL total; 8 result lanes store directly.
__global__ void __launch_bounds__(256, 4)
edge_dot_kernel(const int* __restrict__ src,
                const int* __restrict__ dst,
                float* __restrict__ out, int e, int n) {
    int warp = (blockIdx.x * blockDim.x + threadIdx.x) >> 5;
    int lane = threadIdx.x & 31;
    int e0 = warp * 8;
    if (e0 >= e) return;

    // lanes 0..7 -> src[e0+lane], lanes 8..15 -> dst[e0+lane-8]
    int myidx = 0;
    if (lane < 16) {
        int k = e0 + (lane & 7);
        if (k < e) {
            myidx = (lane < 8) ? __ldg(src + k) : __ldg(dst + k);
            if ((unsigned)myidx >= (unsigned)n) myidx = 0;  // defensive
        }
    }

    const int laneHi = lane >> 4;    // 0: even edges, 1: odd edges
    const int lane15 = lane & 15;
    const uint4* base = reinterpret_cast<const uint4*>(g_xh);  // 16 uint4/row

    // Gather: a[k] = src row of edge 2k+laneHi, b[k] = dst row of same edge.
    uint4 a[4], b[4];
#pragma unroll
    for (int k = 0; k < 4; k++) {
        int rs = __shfl_sync(0xffffffffu, myidx, 2 * k + laneHi);
        a[k] = __ldg(base + (size_t)rs * 16 + lane15);
    }
#pragma unroll
    for (int k = 0; k < 4; k++) {
        int rd = __shfl_sync(0xffffffffu, myidx, 8 + 2 * k + laneHi);
        b[k] = __ldg(base + (size_t)rd * 16 + lane15);
    }

    // Per-lane partial dot over 8 halves, half2 math with 2-term half chains.
    float acc[4];
#pragma unroll
    for (int k = 0; k < 4; k++) {
        __half2 a0 = *reinterpret_cast<__half2*>(&a[k].x);
        __half2 a1 = *reinterpret_cast<__half2*>(&a[k].y);
        __half2 a2 = *reinterpret_cast<__half2*>(&a[k].z);
        __half2 a3 = *reinterpret_cast<__half2*>(&a[k].w);
        __half2 b0 = *reinterpret_cast<__half2*>(&b[k].x);
        __half2 b1 = *reinterpret_cast<__half2*>(&b[k].y);
        __half2 b2 = *reinterpret_cast<__half2*>(&b[k].z);
        __half2 b3 = *reinterpret_cast<__half2*>(&b[k].w);
        __half2 g0 = __hfma2(a1, b1, __hmul2(a0, b0));
        __half2 g1 = __hfma2(a3, b3, __hmul2(a2, b2));
        float2 f0 = __half22float2(g0);
        float2 f1 = __half22float2(g1);
        acc[k] = (f0.x + f0.y) + (f1.x + f1.y);
    }

    // Value-packing butterfly within 16-lane halves (both halves in parallel).
    // Reduce over lane bit 8, pack accumulators by bit 8; reduce bit 4, pack
    // by bit 4; reduce bits 2, 1. Lane's final value index:
    //   k = ((lane>>3)&1) + ((lane&4)?2:0), edge = 2k + laneHi.
#pragma unroll
    for (int k = 0; k < 4; k++)
        acc[k] += __shfl_xor_sync(0xffffffffu, acc[k], 8);
    float m0 = (lane & 8) ? acc[1] : acc[0];
    float m1 = (lane & 8) ? acc[3] : acc[2];
    m0 += __shfl_xor_sync(0xffffffffu, m0, 4);
    m1 += __shfl_xor_sync(0xffffffffu, m1, 4);
    float q = (lane & 4) ? m1 : m0;
    q += __shfl_xor_sync(0xffffffffu, q, 2);
    q += __shfl_xor_sync(0xffffffffu, q, 1);

    if ((lane & 3) == 0) {
        int k = ((lane >> 3) & 1) + ((lane & 4) ? 2 : 0);
        int eidx = e0 + 2 * k + laneHi;
        if (eidx < e) out[eidx] = q;
    }
}

extern "C" void kernel_launch(void* const* d_in, const int* in_sizes, int n_in,
                              void* d_out, int out_size) {
    const float* x   = (const float*)d_in[0];
    const int*   src = (const int*)d_in[1];
    const int*   dst = (const int*)d_in[2];
    float*       out = (float*)d_out;

    int n = in_sizes[0] / D;   // 100000
    int e = in_sizes[1];       // 640000

    int nblk1 = (n + 7) / 8;                 // 8 warps/block
    normalize_kernel<<<nblk1, 256>>>(x, n);

    int warps = (e + 7) / 8;
    int nblk2 = (warps + 7) / 8;
    edge_dot_kernel<<<nblk2, 256>>>(src, dst, out, e, n);
}